// round 13
// baseline (speedup 1.0000x reference)
#include <cuda_runtime.h>

// T=2048, B=1024, H=50, 4H=200. Only batch row B-1 reaches the output
// (reference takes hs[:, -1, :] on the batch axis) and the recurrence is
// batch-independent -> single length-2048 sequence, H=50, on ONE SM.
#define TT 2048
#define BB 1024
#define HH 50
#define NTHREADS 128   // 4 warps, 1 per SMSP; lane pair 2u/2u+1 owns unit u

typedef unsigned long long ull;

__device__ __forceinline__ ull ffma2(ull a, ull b, ull c) {
    ull d;
    asm("fma.rn.f32x2 %0, %1, %2, %3;" : "=l"(d) : "l"(a), "l"(b), "l"(c));
    return d;
}
__device__ __forceinline__ float tanh_fast(float x) {
    float r;
    asm("tanh.approx.f32 %0, %1;" : "=f"(r) : "f"(x));
    return r;
}

__global__ __launch_bounds__(NTHREADS, 1)
void lstm_seq_kernel(const float* __restrict__ x,      // (T, B, 1)
                     const float* __restrict__ W_ih,   // (4H, 1)
                     const float* __restrict__ W_hh,   // (4H, H)
                     const float* __restrict__ b_ih,
                     const float* __restrict__ b_hh,
                     const float* __restrict__ W_lin,  // (1, H)
                     const float* __restrict__ b_lin,
                     float* __restrict__ out)          // T floats
{
    __shared__ __align__(16) float h_s[2][56];  // double buffer; [50..55] pad=0
    __shared__ float xcol[TT];

    const int j    = threadIdx.x;
    const int half = j & 1;                 // 0: gates (i,g)   1: gates (f,o)
    const int u    = j >> 1;                // unit 0..63 (>=50 spare)
    const int uc   = (u < HH) ? u : (HH - 1);
    // rowA: i (even) / f (odd) -- always sigmoid
    // rowB: g (even, tanh) / o (odd, sigmoid)
    const int rowA = half ? (HH + uc)     : uc;
    const int rowB = half ? (3 * HH + uc) : (2 * HH + uc);

    for (int t = j; t < TT; t += NTHREADS) xcol[t] = x[t * BB + (BB - 1)];
    if (j < 56) { h_s[0][j] = 0.0f; h_s[1][j] = 0.0f; }

    // Two weight rows per thread, packed f32x2 (row byte offset row*200).
    // SPARE LANE REPURPOSE: lane (u==50, even) loads W_lin into wpA and
    // b_lin into bsumA, so its uniform matvec computes
    //   preA = b_lin + dot(W_lin, h_{t-1}) = out[t-1]   -- the model output.
    ull wpA[25], wpB[25];
    float bsumA, wihA;
    const bool outlane = (!half) && (u == 50);
    {
        const ull* ra = outlane ? reinterpret_cast<const ull*>(W_lin)
                                : reinterpret_cast<const ull*>(W_hh + rowA * HH);
        const ull* rb = reinterpret_cast<const ull*>(W_hh + rowB * HH);
        #pragma unroll
        for (int k = 0; k < 25; k++) { wpA[k] = ra[k]; wpB[k] = rb[k]; }
        bsumA = outlane ? b_lin[0] : (b_ih[rowA] + b_hh[rowA]);
        wihA  = outlane ? 0.0f     : W_ih[rowA];
    }
    const float bsumB = b_ih[rowB] + b_hh[rowB];
    const float wihB  = W_ih[rowB];
    // activation constants for rowB: tanh (even) vs sigmoid (odd)
    const float ascB  = half ? 0.5f : 1.0f;
    const float amulB = half ? 0.5f : 1.0f;
    const float aaddB = half ? 0.5f : 0.0f;

    float c = 0.0f;   // redundant in both lanes of the pair (bit-identical)
    __syncthreads();

    #pragma unroll 1
    for (int t2 = 0; t2 < TT; t2 += 2) {
        #pragma unroll
        for (int s = 0; s < 2; s++) {
            const int t = t2 + s;
            const float* hsrc = h_s[s];
            float*       hdst = h_s[s ^ 1];
            const float  xv   = xcol[t];
            const float preA0 = fmaf(xv, wihA, bsumA);
            const float preB0 = fmaf(xv, wihB, bsumB);

            // --- two 50-dots sharing one h load (12 LDS.128 + 1 LDS.64) ---
            ull aA0 = 0ull, aA1 = 0ull, aB0 = 0ull, aB1 = 0ull;
            const ulonglong2* h4 = reinterpret_cast<const ulonglong2*>(hsrc);
            #pragma unroll
            for (int k = 0; k < 12; k++) {
                ulonglong2 p = h4[k];
                aA0 = ffma2(wpA[2 * k],     p.x, aA0);
                aA1 = ffma2(wpA[2 * k + 1], p.y, aA1);
                aB0 = ffma2(wpB[2 * k],     p.x, aB0);
                aB1 = ffma2(wpB[2 * k + 1], p.y, aB1);
            }
            {
                ull hl = reinterpret_cast<const ull*>(hsrc)[24];
                aA0 = ffma2(wpA[24], hl, aA0);
                aB0 = ffma2(wpB[24], hl, aB0);
            }
            union { ull uv; float2 f; } uA0, uA1, uB0, uB1;
            uA0.uv = aA0; uA1.uv = aA1; uB0.uv = aB0; uB1.uv = aB1;
            float preA = preA0 + ((uA0.f.x + uA1.f.x) + (uA0.f.y + uA1.f.y));
            float preB = preB0 + ((uB0.f.x + uB1.f.x) + (uB0.f.y + uB1.f.y));

            // --- activations: sigmoid = 0.5 + 0.5*tanh(x/2) ---
            float aAv = fmaf(tanh_fast(preA * 0.5f), 0.5f, 0.5f);     // i / f
            float aBv = fmaf(tanh_fast(preB * ascB), amulB, aaddB);   // g / o

            // --- two INDEPENDENT xor-1 shuffles exchange gates in-pair ---
            float pown = aAv * aBv;           // = i*g on even lanes
            float s1 = __shfl_xor_sync(0xffffffffu, half ? aAv : pown, 1, 32);
            float s2 = __shfl_xor_sync(0xffffffffu, half ? aBv : pown, 1, 32);
            // even: f=s1, o=s2, p=pown ; odd: p=s1, f=aAv, o=aBv
            float fv = half ? aAv : s1;
            float ov = half ? aBv : s2;
            float pv = half ? s1  : pown;

            // --- redundant cell/hidden update (bit-identical both lanes) ---
            c = fmaf(fv, c, pv);
            float hn = ov * tanh_fast(c);
            if (!half) {
                if (u < HH) {
                    hdst[u] = hn;                 // critical STS
                } else if (u == 50 && t > 0) {
                    out[t - 1] = preA;            // model output for step t-1
                }
            }
            __syncthreads();
        }
    }

    // Tail: out[TT-1] = b_lin + dot(W_lin, h_{TT-1}); h_{TT-1} is in h_s[0].
    if (outlane) {
        ull a0 = 0ull, a1 = 0ull;
        const ulonglong2* h4 = reinterpret_cast<const ulonglong2*>(h_s[0]);
        #pragma unroll
        for (int k = 0; k < 12; k++) {
            ulonglong2 p = h4[k];
            a0 = ffma2(wpA[2 * k],     p.x, a0);
            a1 = ffma2(wpA[2 * k + 1], p.y, a1);
        }
        a0 = ffma2(wpA[24], reinterpret_cast<const ull*>(h_s[0])[24], a0);
        union { ull uv; float2 f; } u0, u1;
        u0.uv = a0; u1.uv = a1;
        out[TT - 1] = bsumA + ((u0.f.x + u1.f.x) + (u0.f.y + u1.f.y));
    }
}

extern "C" void kernel_launch(void* const* d_in, const int* in_sizes, int n_in,
                              void* d_out, int out_size) {
    const float* x     = (const float*)d_in[0];
    const float* W_ih  = (const float*)d_in[1];
    const float* W_hh  = (const float*)d_in[2];
    const float* b_ih  = (const float*)d_in[3];
    const float* b_hh  = (const float*)d_in[4];
    const float* W_lin = (const float*)d_in[5];
    const float* b_lin = (const float*)d_in[6];
    lstm_seq_kernel<<<1, NTHREADS>>>(x, W_ih, W_hh, b_ih, b_hh, W_lin, b_lin,
                                     (float*)d_out);
}

// round 14
// speedup vs baseline: 1.4421x; 1.4421x over previous
#include <cuda_runtime.h>

// T=2048, B=1024, H=50, 4H=200. Only batch row B-1 reaches the output
// (reference takes hs[:, -1, :] on the batch axis) and the recurrence is
// batch-independent -> single length-2048 sequence, H=50, on ONE SM.
//
// Champion structure (R7, 394.3us; six later perturbations all regressed):
//   - 128 threads (4 warps, 1/SMSP); lane pair 2u/2u+1 owns hidden unit u
//   - each thread computes TWO gate rows sharing one LDS.128 h load
//   - packed fma.rn.f32x2 matvec, 2 accumulators per row
//   - sigmoid via 0.5 + 0.5*tanh(x/2)  (single MUFU tanh.approx)
//   - two INDEPENDENT xor-1 shuffles exchange gates within the pair
//   - redundant bit-identical c/h update in both lanes
//   - double-buffered h in shared; ONE __syncthreads per step
//   - h history streamed to global; output dot in a parallel epilogue
#define TT 2048
#define BB 1024
#define HH 50
#define NTHREADS 128

// Per-timestep hidden history; output dot handled in parallel epilogue.
__device__ float g_hs[TT * HH];

typedef unsigned long long ull;

__device__ __forceinline__ ull ffma2(ull a, ull b, ull c) {
    ull d;
    asm("fma.rn.f32x2 %0, %1, %2, %3;" : "=l"(d) : "l"(a), "l"(b), "l"(c));
    return d;
}
__device__ __forceinline__ float tanh_fast(float x) {
    float r;
    asm("tanh.approx.f32 %0, %1;" : "=f"(r) : "f"(x));
    return r;
}

__global__ __launch_bounds__(NTHREADS, 1)
void lstm_seq_kernel(const float* __restrict__ x,      // (T, B, 1)
                     const float* __restrict__ W_ih,   // (4H, 1)
                     const float* __restrict__ W_hh,   // (4H, H)
                     const float* __restrict__ b_ih,
                     const float* __restrict__ b_hh,
                     const float* __restrict__ W_lin,  // (1, H)
                     const float* __restrict__ b_lin,
                     float* __restrict__ out)          // T floats
{
    __shared__ __align__(16) float h_s[2][56];  // double buffer
    __shared__ float xcol[TT];

    const int j    = threadIdx.x;
    const int half = j & 1;                 // 0: gates (i,g)   1: gates (f,o)
    const int u    = j >> 1;                // unit 0..63 (>=50 redundant)
    const int uc   = (u < HH) ? u : (HH - 1);
    // rowA: i (even) / f (odd) -- always sigmoid
    // rowB: g (even, tanh) / o (odd, sigmoid)
    const int rowA = half ? (HH + uc)     : uc;
    const int rowB = half ? (3 * HH + uc) : (2 * HH + uc);

    for (int t = j; t < TT; t += NTHREADS) xcol[t] = x[t * BB + (BB - 1)];
    if (j < 56) { h_s[0][j] = 0.0f; h_s[1][j] = 0.0f; }

    // Two weight rows per thread, packed f32x2 (row byte offset j*200, 8B aligned)
    ull wpA[25], wpB[25];
    {
        const ull* ra = reinterpret_cast<const ull*>(W_hh + rowA * HH);
        const ull* rb = reinterpret_cast<const ull*>(W_hh + rowB * HH);
        #pragma unroll
        for (int k = 0; k < 25; k++) { wpA[k] = ra[k]; wpB[k] = rb[k]; }
    }
    const float bsumA = b_ih[rowA] + b_hh[rowA];
    const float bsumB = b_ih[rowB] + b_hh[rowB];
    const float wihA  = W_ih[rowA];
    const float wihB  = W_ih[rowB];
    // activation constants for rowB: tanh (even) vs sigmoid (odd)
    const float ascB  = half ? 0.5f : 1.0f;
    const float amulB = half ? 0.5f : 1.0f;
    const float aaddB = half ? 0.5f : 0.0f;

    float c = 0.0f;   // redundant in both lanes of the pair (bit-identical)
    __syncthreads();

    #pragma unroll 1
    for (int t2 = 0; t2 < TT; t2 += 2) {
        #pragma unroll
        for (int s = 0; s < 2; s++) {
            const int t = t2 + s;
            const float* hsrc = h_s[s];
            float*       hdst = h_s[s ^ 1];
            const float  xv   = xcol[t];
            float preA0 = fmaf(xv, wihA, bsumA);
            float preB0 = fmaf(xv, wihB, bsumB);

            // --- two 50-dots sharing one h load (12 LDS.128 + 1 LDS.64) ---
            ull aA0 = 0ull, aA1 = 0ull, aB0 = 0ull, aB1 = 0ull;
            const ulonglong2* h4 = reinterpret_cast<const ulonglong2*>(hsrc);
            #pragma unroll
            for (int k = 0; k < 12; k++) {
                ulonglong2 p = h4[k];
                aA0 = ffma2(wpA[2 * k],     p.x, aA0);
                aA1 = ffma2(wpA[2 * k + 1], p.y, aA1);
                aB0 = ffma2(wpB[2 * k],     p.x, aB0);
                aB1 = ffma2(wpB[2 * k + 1], p.y, aB1);
            }
            {
                ull hl = reinterpret_cast<const ull*>(hsrc)[24];
                aA0 = ffma2(wpA[24], hl, aA0);
                aB0 = ffma2(wpB[24], hl, aB0);
            }
            union { ull uv; float2 f; } uA0, uA1, uB0, uB1;
            uA0.uv = aA0; uA1.uv = aA1; uB0.uv = aB0; uB1.uv = aB1;
            float preA = preA0 + ((uA0.f.x + uA1.f.x) + (uA0.f.y + uA1.f.y));
            float preB = preB0 + ((uB0.f.x + uB1.f.x) + (uB0.f.y + uB1.f.y));

            // --- activations: sigmoid = 0.5 + 0.5*tanh(x/2) ---
            float aAv = fmaf(tanh_fast(preA * 0.5f), 0.5f, 0.5f);     // i / f
            float aBv = fmaf(tanh_fast(preB * ascB), amulB, aaddB);   // g / o

            // --- two INDEPENDENT xor-1 shuffles exchange gates in-pair ---
            float pown = aAv * aBv;           // = i*g on even lanes
            float s1 = __shfl_xor_sync(0xffffffffu, half ? aAv : pown, 1, 32);
            float s2 = __shfl_xor_sync(0xffffffffu, half ? aBv : pown, 1, 32);
            // even: f=s1, o=s2, p=pown ; odd: p=s1, f=aAv, o=aBv
            float fv = half ? aAv : s1;
            float ov = half ? aBv : s2;
            float pv = half ? s1  : pown;

            // --- redundant cell/hidden update (bit-identical both lanes) ---
            c = fmaf(fv, c, pv);
            float hn = ov * tanh_fast(c);
            if (!half && u < HH) {
                hdst[u] = hn;                 // critical STS
                g_hs[t * HH + u] = hn;        // fire-and-forget for epilogue
            }
            __syncthreads();
        }
    }

    // Epilogue: out[t] = dot(h_t, W_lin) + b_lin, parallel over t.
    const float bl = b_lin[0];
    for (int t = j; t < TT; t += NTHREADS) {
        float s = bl;
        #pragma unroll
        for (int k = 0; k < HH; k++) s += g_hs[t * HH + k] * W_lin[k];
        out[t] = s;
    }
}

extern "C" void kernel_launch(void* const* d_in, const int* in_sizes, int n_in,
                              void* d_out, int out_size) {
    const float* x     = (const float*)d_in[0];
    const float* W_ih  = (const float*)d_in[1];
    const float* W_hh  = (const float*)d_in[2];
    const float* b_ih  = (const float*)d_in[3];
    const float* b_hh  = (const float*)d_in[4];
    const float* W_lin = (const float*)d_in[5];
    const float* b_lin = (const float*)d_in[6];
    lstm_seq_kernel<<<1, NTHREADS>>>(x, W_ih, W_hh, b_ih, b_hh, W_lin, b_lin,
                                     (float*)d_out);
}

// round 15
// speedup vs baseline: 1.5559x; 1.0789x over previous
#include <cuda_runtime.h>

// T=2048, B=1024, H=50, 4H=200. Only batch row B-1 reaches the output
// (reference takes hs[:, -1, :] on the batch axis) and the recurrence is
// batch-independent -> single length-2048 sequence, H=50, on ONE SM.
//
// R15: champion layout (128 thr, 4 warps, pair 2u/2u+1 owns unit u) but the
// h-dot is split WITHIN the pair to cut SM-level LSU ops ~40%:
//   even lane: all 4 gate rows x h-pairs 0..11   (pair 12 weight zeroed)
//   odd  lane: all 4 gate rows x h-pairs 12..24
//   2 packed xor-1 shuffles combine partials -> BOTH lanes hold all 4 gates
//   -> no separate gate-exchange shuffles; redundant bit-identical update.
#define TT 2048
#define BB 1024
#define HH 50
#define NTHREADS 128

// Per-timestep hidden history; output dot handled in parallel epilogue.
__device__ float g_hs[TT * HH];

typedef unsigned long long ull;

__device__ __forceinline__ ull ffma2(ull a, ull b, ull c) {
    ull d;
    asm("fma.rn.f32x2 %0, %1, %2, %3;" : "=l"(d) : "l"(a), "l"(b), "l"(c));
    return d;
}
__device__ __forceinline__ ull fadd2(ull a, ull b) {
    ull d;
    asm("add.rn.f32x2 %0, %1, %2;" : "=l"(d) : "l"(a), "l"(b));
    return d;
}
__device__ __forceinline__ float tanh_fast(float x) {
    float r;
    asm("tanh.approx.f32 %0, %1;" : "=f"(r) : "f"(x));
    return r;
}
__device__ __forceinline__ float f2lo(ull v) { union { ull u; float2 f; } w; w.u = v; return w.f.x; }
__device__ __forceinline__ float f2hi(ull v) { union { ull u; float2 f; } w; w.u = v; return w.f.y; }
__device__ __forceinline__ ull pack2(float a, float b) {
    union { ull u; float2 f; } w; w.f.x = a; w.f.y = b; return w.u;
}

__global__ __launch_bounds__(NTHREADS, 1)
void lstm_seq_kernel(const float* __restrict__ x,      // (T, B, 1)
                     const float* __restrict__ W_ih,   // (4H, 1)
                     const float* __restrict__ W_hh,   // (4H, H)
                     const float* __restrict__ b_ih,
                     const float* __restrict__ b_hh,
                     const float* __restrict__ W_lin,  // (1, H)
                     const float* __restrict__ b_lin,
                     float* __restrict__ out)          // T floats
{
    __shared__ __align__(16) float h_s[2][56];  // double buffer; [50..55] pad=0
    __shared__ float xcol[TT];

    const int j    = threadIdx.x;
    const int half = j & 1;                 // 0: h-pairs 0..11  1: h-pairs 12..24
    const int u    = j >> 1;                // unit 0..63 (>=50 redundant)
    const int uc   = (u < HH) ? u : (HH - 1);
    const int base = half ? 12 : 0;         // first h-pair this lane covers

    // All four gate rows of unit uc.
    const int ri = uc;
    const int rf = HH + uc;
    const int rg = 2 * HH + uc;
    const int ro = 3 * HH + uc;

    for (int t = j; t < TT; t += NTHREADS) xcol[t] = x[t * BB + (BB - 1)];
    if (j < 56) { h_s[0][j] = 0.0f; h_s[1][j] = 0.0f; }

    // 13 packed weight pairs per row over this lane's h-half.
    // Even lane's 13th slot (pair 12) is zero so only the odd lane counts it.
    ull wi[13], wf[13], wg[13], wo[13];
    {
        const ull* pwi = reinterpret_cast<const ull*>(W_hh + ri * HH);
        const ull* pwf = reinterpret_cast<const ull*>(W_hh + rf * HH);
        const ull* pwg = reinterpret_cast<const ull*>(W_hh + rg * HH);
        const ull* pwo = reinterpret_cast<const ull*>(W_hh + ro * HH);
        #pragma unroll
        for (int k = 0; k < 13; k++) {
            bool v = half || (k < 12);      // even lane zeroes k==12
            int pi = base + k;              // 0..12 (even) / 12..24 (odd)
            wi[k] = v ? pwi[pi] : 0ull;
            wf[k] = v ? pwf[pi] : 0ull;
            wg[k] = v ? pwg[pi] : 0ull;
            wo[k] = v ? pwo[pi] : 0ull;
        }
    }
    const float bsi = b_ih[ri] + b_hh[ri], wihi = W_ih[ri];
    const float bsf = b_ih[rf] + b_hh[rf], wihf = W_ih[rf];
    const float bsg = b_ih[rg] + b_hh[rg], wihg = W_ih[rg];
    const float bso = b_ih[ro] + b_hh[ro], wiho = W_ih[ro];

    float c = 0.0f;   // redundant in both lanes of the pair (bit-identical)
    __syncthreads();

    #pragma unroll 1
    for (int t2 = 0; t2 < TT; t2 += 2) {
        #pragma unroll
        for (int s = 0; s < 2; s++) {
            const int t = t2 + s;
            const float* hsrc = h_s[s];
            float*       hdst = h_s[s ^ 1];
            const float  xv   = xcol[t];

            // --- half-dots: 4 rows x 13 pairs over this lane's h-half ---
            // h loads: 6 x LDS.128 (pairs base..base+11) + 1 x LDS.64 (pair base+12)
            ull ai0 = 0ull, ai1 = 0ull, af0 = 0ull, af1 = 0ull;
            ull ag0 = 0ull, ag1 = 0ull, ao0 = 0ull, ao1 = 0ull;
            const ulonglong2* h4 =
                reinterpret_cast<const ulonglong2*>(
                    reinterpret_cast<const ull*>(hsrc) + base);
            #pragma unroll
            for (int k = 0; k < 6; k++) {
                ulonglong2 p = h4[k];
                ai0 = ffma2(wi[2 * k],     p.x, ai0);
                ai1 = ffma2(wi[2 * k + 1], p.y, ai1);
                af0 = ffma2(wf[2 * k],     p.x, af0);
                af1 = ffma2(wf[2 * k + 1], p.y, af1);
                ag0 = ffma2(wg[2 * k],     p.x, ag0);
                ag1 = ffma2(wg[2 * k + 1], p.y, ag1);
                ao0 = ffma2(wo[2 * k],     p.x, ao0);
                ao1 = ffma2(wo[2 * k + 1], p.y, ao1);
            }
            {
                ull hl = reinterpret_cast<const ull*>(hsrc)[base + 12];
                ai0 = ffma2(wi[12], hl, ai0);
                af0 = ffma2(wf[12], hl, af0);
                ag0 = ffma2(wg[12], hl, ag0);
                ao0 = ffma2(wo[12], hl, ao0);
            }
            ull rI = fadd2(ai0, ai1), rF = fadd2(af0, af1);
            ull rG = fadd2(ag0, ag1), rO = fadd2(ao0, ao1);
            float pi_ = f2lo(rI) + f2hi(rI);
            float pf_ = f2lo(rF) + f2hi(rF);
            float pg_ = f2lo(rG) + f2hi(rG);
            float po_ = f2lo(rO) + f2hi(rO);

            // --- cross-half combine: 2 packed xor-1 shuffles, fixed order ---
            ull m1 = pack2(pi_, pf_);
            ull m2 = pack2(pg_, po_);
            ull o1 = __shfl_xor_sync(0xffffffffu, m1, 1, 32);
            ull o2 = __shfl_xor_sync(0xffffffffu, m2, 1, 32);
            ull lo1 = half ? o1 : m1, hi1 = half ? m1 : o1;
            ull lo2 = half ? o2 : m2, hi2 = half ? m2 : o2;
            float preI = fmaf(xv, wihi, bsi) + (f2lo(lo1) + f2lo(hi1));
            float preF = fmaf(xv, wihf, bsf) + (f2hi(lo1) + f2hi(hi1));
            float preG = fmaf(xv, wihg, bsg) + (f2lo(lo2) + f2lo(hi2));
            float preO = fmaf(xv, wiho, bso) + (f2hi(lo2) + f2hi(hi2));

            // --- activations: sigmoid = 0.5 + 0.5*tanh(x/2); g = tanh ---
            float iv = fmaf(tanh_fast(preI * 0.5f), 0.5f, 0.5f);
            float fv = fmaf(tanh_fast(preF * 0.5f), 0.5f, 0.5f);
            float gv = tanh_fast(preG);
            float ov = fmaf(tanh_fast(preO * 0.5f), 0.5f, 0.5f);

            // --- redundant cell/hidden update (bit-identical both lanes) ---
            c = fmaf(fv, c, iv * gv);
            float hn = ov * tanh_fast(c);
            if (!half && u < HH) hdst[u] = hn;          // critical STS
            if ( half && u < HH) g_hs[t * HH + u] = hn; // off-path STG
            __syncthreads();
        }
    }

    // Epilogue: out[t] = dot(h_t, W_lin) + b_lin, parallel over t.
    const float bl = b_lin[0];
    for (int t = j; t < TT; t += NTHREADS) {
        float s = bl;
        #pragma unroll
        for (int k = 0; k < HH; k++) s += g_hs[t * HH + k] * W_lin[k];
        out[t] = s;
    }
}

extern "C" void kernel_launch(void* const* d_in, const int* in_sizes, int n_in,
                              void* d_out, int out_size) {
    const float* x     = (const float*)d_in[0];
    const float* W_ih  = (const float*)d_in[1];
    const float* W_hh  = (const float*)d_in[2];
    const float* b_ih  = (const float*)d_in[3];
    const float* b_hh  = (const float*)d_in[4];
    const float* W_lin = (const float*)d_in[5];
    const float* b_lin = (const float*)d_in[6];
    lstm_seq_kernel<<<1, NTHREADS>>>(x, W_ih, W_hh, b_ih, b_hh, W_lin, b_lin,
                                     (float*)d_out);
}

// round 16
// speedup vs baseline: 1.6172x; 1.0394x over previous
#include <cuda_runtime.h>

// T=2048, B=1024, H=50, 4H=200. Only batch row B-1 reaches the output
// (reference takes hs[:, -1, :] on the batch axis) and the recurrence is
// batch-independent -> single length-2048 sequence, H=50, on ONE SM.
//
// R16 = R15 champion loop (364.8us) unchanged; epilogue (out[t] dot) moved to
// a SECOND kernel so the sequential SM stops at the last timestep and the
// embarrassingly-parallel output dot runs wide on other SMs.
#define TT 2048
#define BB 1024
#define HH 50
#define NTHREADS 128

// Per-timestep hidden history, produced by the sequential kernel and
// consumed by the output kernel (stream-ordered).
__device__ float g_hs[TT * HH];

typedef unsigned long long ull;

__device__ __forceinline__ ull ffma2(ull a, ull b, ull c) {
    ull d;
    asm("fma.rn.f32x2 %0, %1, %2, %3;" : "=l"(d) : "l"(a), "l"(b), "l"(c));
    return d;
}
__device__ __forceinline__ ull fadd2(ull a, ull b) {
    ull d;
    asm("add.rn.f32x2 %0, %1, %2;" : "=l"(d) : "l"(a), "l"(b));
    return d;
}
__device__ __forceinline__ float tanh_fast(float x) {
    float r;
    asm("tanh.approx.f32 %0, %1;" : "=f"(r) : "f"(x));
    return r;
}
__device__ __forceinline__ float f2lo(ull v) { union { ull u; float2 f; } w; w.u = v; return w.f.x; }
__device__ __forceinline__ float f2hi(ull v) { union { ull u; float2 f; } w; w.u = v; return w.f.y; }
__device__ __forceinline__ ull pack2(float a, float b) {
    union { ull u; float2 f; } w; w.f.x = a; w.f.y = b; return w.u;
}

__global__ __launch_bounds__(NTHREADS, 1)
void lstm_seq_kernel(const float* __restrict__ x,      // (T, B, 1)
                     const float* __restrict__ W_ih,   // (4H, 1)
                     const float* __restrict__ W_hh,   // (4H, H)
                     const float* __restrict__ b_ih,
                     const float* __restrict__ b_hh)
{
    __shared__ __align__(16) float h_s[2][56];  // double buffer; [50..55] pad=0
    __shared__ float xcol[TT];

    const int j    = threadIdx.x;
    const int half = j & 1;                 // 0: h-pairs 0..11  1: h-pairs 12..24
    const int u    = j >> 1;                // unit 0..63 (>=50 redundant)
    const int uc   = (u < HH) ? u : (HH - 1);
    const int base = half ? 12 : 0;         // first h-pair this lane covers

    // All four gate rows of unit uc.
    const int ri = uc;
    const int rf = HH + uc;
    const int rg = 2 * HH + uc;
    const int ro = 3 * HH + uc;

    for (int t = j; t < TT; t += NTHREADS) xcol[t] = x[t * BB + (BB - 1)];
    if (j < 56) { h_s[0][j] = 0.0f; h_s[1][j] = 0.0f; }

    // 13 packed weight pairs per row over this lane's h-half.
    // Even lane's 13th slot (pair 12) is zero so only the odd lane counts it.
    ull wi[13], wf[13], wg[13], wo[13];
    {
        const ull* pwi = reinterpret_cast<const ull*>(W_hh + ri * HH);
        const ull* pwf = reinterpret_cast<const ull*>(W_hh + rf * HH);
        const ull* pwg = reinterpret_cast<const ull*>(W_hh + rg * HH);
        const ull* pwo = reinterpret_cast<const ull*>(W_hh + ro * HH);
        #pragma unroll
        for (int k = 0; k < 13; k++) {
            bool v = half || (k < 12);      // even lane zeroes k==12
            int pi = base + k;              // 0..12 (even) / 12..24 (odd)
            wi[k] = v ? pwi[pi] : 0ull;
            wf[k] = v ? pwf[pi] : 0ull;
            wg[k] = v ? pwg[pi] : 0ull;
            wo[k] = v ? pwo[pi] : 0ull;
        }
    }
    const float bsi = b_ih[ri] + b_hh[ri], wihi = W_ih[ri];
    const float bsf = b_ih[rf] + b_hh[rf], wihf = W_ih[rf];
    const float bsg = b_ih[rg] + b_hh[rg], wihg = W_ih[rg];
    const float bso = b_ih[ro] + b_hh[ro], wiho = W_ih[ro];

    float c = 0.0f;   // redundant in both lanes of the pair (bit-identical)
    __syncthreads();

    #pragma unroll 1
    for (int t2 = 0; t2 < TT; t2 += 2) {
        #pragma unroll
        for (int s = 0; s < 2; s++) {
            const int t = t2 + s;
            const float* hsrc = h_s[s];
            float*       hdst = h_s[s ^ 1];
            const float  xv   = xcol[t];

            // --- half-dots: 4 rows x 13 pairs over this lane's h-half ---
            ull ai0 = 0ull, ai1 = 0ull, af0 = 0ull, af1 = 0ull;
            ull ag0 = 0ull, ag1 = 0ull, ao0 = 0ull, ao1 = 0ull;
            const ulonglong2* h4 =
                reinterpret_cast<const ulonglong2*>(
                    reinterpret_cast<const ull*>(hsrc) + base);
            #pragma unroll
            for (int k = 0; k < 6; k++) {
                ulonglong2 p = h4[k];
                ai0 = ffma2(wi[2 * k],     p.x, ai0);
                ai1 = ffma2(wi[2 * k + 1], p.y, ai1);
                af0 = ffma2(wf[2 * k],     p.x, af0);
                af1 = ffma2(wf[2 * k + 1], p.y, af1);
                ag0 = ffma2(wg[2 * k],     p.x, ag0);
                ag1 = ffma2(wg[2 * k + 1], p.y, ag1);
                ao0 = ffma2(wo[2 * k],     p.x, ao0);
                ao1 = ffma2(wo[2 * k + 1], p.y, ao1);
            }
            {
                ull hl = reinterpret_cast<const ull*>(hsrc)[base + 12];
                ai0 = ffma2(wi[12], hl, ai0);
                af0 = ffma2(wf[12], hl, af0);
                ag0 = ffma2(wg[12], hl, ag0);
                ao0 = ffma2(wo[12], hl, ao0);
            }
            ull rI = fadd2(ai0, ai1), rF = fadd2(af0, af1);
            ull rG = fadd2(ag0, ag1), rO = fadd2(ao0, ao1);
            float pi_ = f2lo(rI) + f2hi(rI);
            float pf_ = f2lo(rF) + f2hi(rF);
            float pg_ = f2lo(rG) + f2hi(rG);
            float po_ = f2lo(rO) + f2hi(rO);

            // --- cross-half combine: 2 packed xor-1 shuffles, fixed order ---
            ull m1 = pack2(pi_, pf_);
            ull m2 = pack2(pg_, po_);
            ull o1 = __shfl_xor_sync(0xffffffffu, m1, 1, 32);
            ull o2 = __shfl_xor_sync(0xffffffffu, m2, 1, 32);
            ull lo1 = half ? o1 : m1, hi1 = half ? m1 : o1;
            ull lo2 = half ? o2 : m2, hi2 = half ? m2 : o2;
            float preI = fmaf(xv, wihi, bsi) + (f2lo(lo1) + f2lo(hi1));
            float preF = fmaf(xv, wihf, bsf) + (f2hi(lo1) + f2hi(hi1));
            float preG = fmaf(xv, wihg, bsg) + (f2lo(lo2) + f2lo(hi2));
            float preO = fmaf(xv, wiho, bso) + (f2hi(lo2) + f2hi(hi2));

            // --- activations: sigmoid = 0.5 + 0.5*tanh(x/2); g = tanh ---
            float iv = fmaf(tanh_fast(preI * 0.5f), 0.5f, 0.5f);
            float fv = fmaf(tanh_fast(preF * 0.5f), 0.5f, 0.5f);
            float gv = tanh_fast(preG);
            float ov = fmaf(tanh_fast(preO * 0.5f), 0.5f, 0.5f);

            // --- redundant cell/hidden update (bit-identical both lanes) ---
            c = fmaf(fv, c, iv * gv);
            float hn = ov * tanh_fast(c);
            if (!half && u < HH) hdst[u] = hn;          // critical STS
            if ( half && u < HH) g_hs[t * HH + u] = hn; // off-path STG
            __syncthreads();
        }
    }
}

// Output dot, massively parallel on other SMs: out[t] = h_t . W_lin + b_lin.
__global__ __launch_bounds__(256)
void out_kernel(const float* __restrict__ W_lin,   // (1, H)
                const float* __restrict__ b_lin,   // (1,)
                float* __restrict__ out)           // T floats
{
    const int t = blockIdx.x * 256 + threadIdx.x;
    if (t >= TT) return;
    const float* hr = g_hs + t * HH;
    float s = b_lin[0];
    #pragma unroll
    for (int k = 0; k < HH; k++) s = fmaf(hr[k], W_lin[k], s);
    out[t] = s;
}

extern "C" void kernel_launch(void* const* d_in, const int* in_sizes, int n_in,
                              void* d_out, int out_size) {
    const float* x     = (const float*)d_in[0];
    const float* W_ih  = (const float*)d_in[1];
    const float* W_hh  = (const float*)d_in[2];
    const float* b_ih  = (const float*)d_in[3];
    const float* b_hh  = (const float*)d_in[4];
    const float* W_lin = (const float*)d_in[5];
    const float* b_lin = (const float*)d_in[6];
    lstm_seq_kernel<<<1, NTHREADS>>>(x, W_ih, W_hh, b_ih, b_hh);
    out_kernel<<<TT / 256, 256>>>(W_lin, b_lin, (float*)d_out);
}